// round 1
// baseline (speedup 1.0000x reference)
#include <cuda_runtime.h>
#include <math.h>

// ---------------- scratch (device globals; no allocs allowed) ----------------
__device__ float g_K1[32 * 32];               // [co][tap32] (25 used, padded)
__device__ float g_K2[64 * 32 * 32];          // [co][ci][tap32]
__device__ float g_out1[4096 * 32 * 14 * 14]; // conv1+pool output
__device__ float g_out2[4096 * 64 * 7 * 7];   // conv2+pool output (= fc1 input, flattened)
__device__ float g_h[4096 * 128];             // fc1 output

// ---------------- DCLS kernel construction (gather, deterministic) ----------
// layer==0: w1 (32,1,16) -> g_K1 ; layer==1: w2 (64,32,32) -> g_K2
__global__ void build_dcls(const float* __restrict__ w, const float* __restrict__ p,
                           int Co, int Ci, int Kc, int layer) {
    int t = blockIdx.x * blockDim.x + threadIdx.x;
    if (t >= Co * Ci) return;
    float acc[25];
#pragma unroll
    for (int j = 0; j < 25; j++) acc[j] = 0.f;
    int base = t * Kc;           // (co*Ci+ci)*Kc
    int pstride = Co * Ci * Kc;  // p: (2,Co,Ci,Kc)
    for (int kc = 0; kc < Kc; kc++) {
        float ww = w[base + kc];
        float p1 = p[base + kc];
        float p2 = p[pstride + base + kc];
        p1 = fminf(fmaxf(p1, -2.f), 2.f) + 2.f;   // in [0,4]
        p2 = fminf(fmaxf(p2, -2.f), 2.f) + 2.f;
        int i1 = (int)floorf(p1), i2 = (int)floorf(p2);
        float r1 = p1 - (float)i1, r2 = p2 - (float)i2;
        acc[i1 * 5 + i2] += ww * (1.f - r1) * (1.f - r2);
        if (i1 + 1 < 5)               acc[(i1 + 1) * 5 + i2]     += ww * r1 * (1.f - r2);
        if (i2 + 1 < 5)               acc[i1 * 5 + (i2 + 1)]     += ww * (1.f - r1) * r2;
        if (i1 + 1 < 5 && i2 + 1 < 5) acc[(i1 + 1) * 5 + i2 + 1] += ww * r1 * r2;
    }
    float* o = (layer == 0 ? g_K1 : g_K2) + t * 32;
#pragma unroll
    for (int j = 0; j < 32; j++) o[j] = (j < 25) ? acc[j] : 0.f;
}

// ---------------- conv1 (1->32, 5x5, pad2) + bias + relu + maxpool2 ---------
// one block per image, 256 threads. smem: padded 32x32 input + K1.
__global__ __launch_bounds__(256) void conv1_pool(const float* __restrict__ x,
                                                  const float* __restrict__ b1) {
    __shared__ float s_in[32 * 33];
    __shared__ float s_w[32 * 32];
    int b = blockIdx.x;
    int tid = threadIdx.x;
    for (int i = tid; i < 32 * 33; i += 256) s_in[i] = 0.f;
    for (int i = tid; i < 32 * 32; i += 256) s_w[i] = g_K1[i];
    __syncthreads();
    const float* xb = x + b * 784;
    for (int i = tid; i < 784; i += 256) {
        int y = i / 28, xx = i - y * 28;
        s_in[(y + 2) * 33 + (xx + 2)] = xb[i];
    }
    __syncthreads();

    int co = tid >> 3;   // 0..31
    int s  = tid & 7;    // 0..7
    float wreg[25];
#pragma unroll
    for (int j = 0; j < 25; j++) wreg[j] = s_w[co * 32 + j];
    float bias = b1[co];
    float* ob = g_out1 + (b * 32 + co) * 196;

    for (int pos = s; pos < 196; pos += 8) {
        int oy = pos / 14, ox = pos - oy * 14;
        const float* pbase = s_in + (2 * oy) * 33 + 2 * ox;
        float xin[6][6];
#pragma unroll
        for (int r = 0; r < 6; r++)
#pragma unroll
            for (int c = 0; c < 6; c++) xin[r][c] = pbase[r * 33 + c];
        float a00 = 0.f, a01 = 0.f, a10 = 0.f, a11 = 0.f;
#pragma unroll
        for (int ky = 0; ky < 5; ky++)
#pragma unroll
            for (int kx = 0; kx < 5; kx++) {
                float w = wreg[ky * 5 + kx];
                a00 = fmaf(w, xin[ky][kx],         a00);
                a01 = fmaf(w, xin[ky][kx + 1],     a01);
                a10 = fmaf(w, xin[ky + 1][kx],     a10);
                a11 = fmaf(w, xin[ky + 1][kx + 1], a11);
            }
        float m = fmaxf(fmaxf(a00, a01), fmaxf(a10, a11));
        ob[pos] = fmaxf(m + bias, 0.f);
    }
}

// ---------------- conv2 (32->64, 5x5, pad2) + bias + relu + maxpool2 --------
// one block per image, 448 threads = 16 co-groups x 7 oy x 4 ox-pairs.
// Each thread: 4 output channels x (2 conv rows x 4 conv cols) register tile.
__global__ __launch_bounds__(448) void conv2_pool(const float* __restrict__ b2) {
    __shared__ float s_in[32 * 360];   // 32 ch, 18 rows, stride 20 (zero padded)
    int b = blockIdx.x;
    int tid = threadIdx.x;
    for (int i = tid; i < 32 * 360; i += 448) s_in[i] = 0.f;
    __syncthreads();
    const float* inb = g_out1 + b * 6272;
    for (int i = tid; i < 6272; i += 448) {
        int ci = i / 196;
        int r = i - ci * 196;
        int y = r / 14, xx = r - y * 14;
        s_in[ci * 360 + (y + 2) * 20 + (xx + 2)] = inb[i];
    }
    __syncthreads();

    int g   = tid / 28;          // 0..15 -> co group
    int rem = tid - g * 28;
    int oy  = rem >> 2;          // 0..6
    int oxp = rem & 3;           // 0..3  (conv cols 4*oxp .. 4*oxp+3)
    int co0 = g * 4;

    float acc[4][8];             // [c4][conv_row*4 + conv_col]
#pragma unroll
    for (int a = 0; a < 4; a++)
#pragma unroll
        for (int j = 0; j < 8; j++) acc[a][j] = 0.f;

    const float* sbase = s_in + (2 * oy) * 20 + 4 * oxp;

    for (int ci = 0; ci < 32; ci++) {
        float xin[6][8];
        const float* pb = sbase + ci * 360;
#pragma unroll
        for (int rr = 0; rr < 6; rr++)
#pragma unroll
            for (int cc = 0; cc < 8; cc++) xin[rr][cc] = pb[rr * 20 + cc];

#pragma unroll
        for (int c4 = 0; c4 < 4; c4++) {
            const float4* wp = (const float4*)(g_K2 + ((co0 + c4) * 32 + ci) * 32);
            float w[28];
#pragma unroll
            for (int jj = 0; jj < 7; jj++) ((float4*)w)[jj] = wp[jj];
#pragma unroll
            for (int ky = 0; ky < 5; ky++)
#pragma unroll
                for (int kx = 0; kx < 5; kx++) {
                    float wv = w[ky * 5 + kx];
#pragma unroll
                    for (int cr = 0; cr < 2; cr++)
#pragma unroll
                        for (int cx = 0; cx < 4; cx++)
                            acc[c4][cr * 4 + cx] =
                                fmaf(wv, xin[cr + ky][cx + kx], acc[c4][cr * 4 + cx]);
                }
        }
    }

    // bias + relu + 2x2 maxpool (relu(max(v)+b) == max(relu(v+b)))
#pragma unroll
    for (int c4 = 0; c4 < 4; c4++) {
        float bias = b2[co0 + c4];
#pragma unroll
        for (int px = 0; px < 2; px++) {
            int ox = 2 * oxp + px;
            if (ox < 7) {
                float m = fmaxf(fmaxf(acc[c4][2 * px], acc[c4][2 * px + 1]),
                                fmaxf(acc[c4][4 + 2 * px], acc[c4][4 + 2 * px + 1]));
                g_out2[((b * 64 + co0 + c4) * 7 + oy) * 7 + ox] = fmaxf(m + bias, 0.f);
            }
        }
    }
}

// ---------------- fc1: (4096,3136) x (128,3136)^T + bias, relu -> g_h -------
__global__ __launch_bounds__(256) void fc1_gemm(const float* __restrict__ W,
                                                const float* __restrict__ bias) {
    __shared__ float As[32][64];
    __shared__ float Bs[32][64];
    int tid = threadIdx.x;
    int row0 = blockIdx.x * 64;
    int col0 = blockIdx.y * 64;
    const float* A = g_out2;

    int lr  = tid >> 2;         // 0..63 (tile row / col for loads)
    int lk4 = (tid & 3) << 3;   // 0,8,16,24
    int tm  = tid >> 4;         // 0..15
    int tn  = tid & 15;         // 0..15

    float acc[4][4];
#pragma unroll
    for (int i = 0; i < 4; i++)
#pragma unroll
        for (int j = 0; j < 4; j++) acc[i][j] = 0.f;

    for (int k0 = 0; k0 < 3136; k0 += 32) {
        float4 a0 = *(const float4*)(A + (row0 + lr) * 3136 + k0 + lk4);
        float4 a1 = *(const float4*)(A + (row0 + lr) * 3136 + k0 + lk4 + 4);
        float4 w0 = *(const float4*)(W + (col0 + lr) * 3136 + k0 + lk4);
        float4 w1 = *(const float4*)(W + (col0 + lr) * 3136 + k0 + lk4 + 4);
        __syncthreads();
        As[lk4 + 0][lr] = a0.x; As[lk4 + 1][lr] = a0.y;
        As[lk4 + 2][lr] = a0.z; As[lk4 + 3][lr] = a0.w;
        As[lk4 + 4][lr] = a1.x; As[lk4 + 5][lr] = a1.y;
        As[lk4 + 6][lr] = a1.z; As[lk4 + 7][lr] = a1.w;
        Bs[lk4 + 0][lr] = w0.x; Bs[lk4 + 1][lr] = w0.y;
        Bs[lk4 + 2][lr] = w0.z; Bs[lk4 + 3][lr] = w0.w;
        Bs[lk4 + 4][lr] = w1.x; Bs[lk4 + 5][lr] = w1.y;
        Bs[lk4 + 6][lr] = w1.z; Bs[lk4 + 7][lr] = w1.w;
        __syncthreads();
#pragma unroll
        for (int kk = 0; kk < 32; kk++) {
            float4 av = *(const float4*)&As[kk][tm * 4];
            float4 bv = *(const float4*)&Bs[kk][tn * 4];
            acc[0][0] = fmaf(av.x, bv.x, acc[0][0]);
            acc[0][1] = fmaf(av.x, bv.y, acc[0][1]);
            acc[0][2] = fmaf(av.x, bv.z, acc[0][2]);
            acc[0][3] = fmaf(av.x, bv.w, acc[0][3]);
            acc[1][0] = fmaf(av.y, bv.x, acc[1][0]);
            acc[1][1] = fmaf(av.y, bv.y, acc[1][1]);
            acc[1][2] = fmaf(av.y, bv.z, acc[1][2]);
            acc[1][3] = fmaf(av.y, bv.w, acc[1][3]);
            acc[2][0] = fmaf(av.z, bv.x, acc[2][0]);
            acc[2][1] = fmaf(av.z, bv.y, acc[2][1]);
            acc[2][2] = fmaf(av.z, bv.z, acc[2][2]);
            acc[2][3] = fmaf(av.z, bv.w, acc[2][3]);
            acc[3][0] = fmaf(av.w, bv.x, acc[3][0]);
            acc[3][1] = fmaf(av.w, bv.y, acc[3][1]);
            acc[3][2] = fmaf(av.w, bv.z, acc[3][2]);
            acc[3][3] = fmaf(av.w, bv.w, acc[3][3]);
        }
    }
#pragma unroll
    for (int i = 0; i < 4; i++)
#pragma unroll
        for (int j = 0; j < 4; j++) {
            int rr = row0 + tm * 4 + i;
            int cc = col0 + tn * 4 + j;
            g_h[rr * 128 + cc] = fmaxf(acc[i][j] + bias[cc], 0.f);
        }
}

// ---------------- fc2: (4096,128) x (10,128)^T + bias -> out ----------------
__global__ void fc2_gemv(const float* __restrict__ W, const float* __restrict__ bias,
                         float* __restrict__ out, int B) {
    int idx = blockIdx.x * blockDim.x + threadIdx.x;
    if (idx >= B * 10) return;
    int row = idx / 10;
    int j = idx - row * 10;
    const float* h = g_h + row * 128;
    const float* w = W + j * 128;
    float s = bias[j];
#pragma unroll
    for (int k = 0; k < 128; k += 4) {
        float4 hv = *(const float4*)(h + k);
        float4 wv = *(const float4*)(w + k);
        s = fmaf(hv.x, wv.x, s);
        s = fmaf(hv.y, wv.y, s);
        s = fmaf(hv.z, wv.z, s);
        s = fmaf(hv.w, wv.w, s);
    }
    out[idx] = s;
}

// ---------------- launch -----------------------------------------------------
extern "C" void kernel_launch(void* const* d_in, const int* in_sizes, int n_in,
                              void* d_out, int out_size) {
    const float* x     = (const float*)d_in[0];
    const float* w1    = (const float*)d_in[1];
    const float* p1    = (const float*)d_in[2];
    const float* b1    = (const float*)d_in[3];
    const float* w2    = (const float*)d_in[4];
    const float* p2    = (const float*)d_in[5];
    const float* b2    = (const float*)d_in[6];
    const float* fc1w  = (const float*)d_in[7];
    const float* fc1b  = (const float*)d_in[8];
    const float* fc2w  = (const float*)d_in[9];
    const float* fc2b  = (const float*)d_in[10];
    float* out = (float*)d_out;

    int B = in_sizes[0] / 784;   // 4096

    build_dcls<<<1, 64>>>(w1, p1, 32, 1, 16, 0);
    build_dcls<<<8, 256>>>(w2, p2, 64, 32, 32, 1);
    conv1_pool<<<B, 256>>>(x, b1);
    conv2_pool<<<B, 448>>>(b2);
    dim3 g1(B / 64, 2);
    fc1_gemm<<<g1, 256>>>(fc1w, fc1b);
    fc2_gemv<<<(B * 10 + 255) / 256, 256>>>(fc2w, fc2b, out, B);
}